// round 16
// baseline (speedup 1.0000x reference)
#include <cuda_runtime.h>
#include <cuda_fp16.h>
#include <math.h>
#include <stdint.h>

// Problem constants
#define Bq   2
#define Sq   2048
#define HIDq 4096
#define Hq   32
#define KVq  8
#define Dq   128
#define Gq   (Hq / KVq)

// Scratch buffers (allocation-free rule: __device__ globals)
__device__ __half g_hsh[(size_t)Bq * Sq * HIDq];        // fp16 hidden_states
__device__ __half g_wqh[(size_t)Hq * Dq * HIDq];        // fp16 wq
__device__ __half g_wkh[(size_t)KVq * Dq * HIDq];       // fp16 wk
__device__ __half g_wvh[(size_t)KVq * Dq * HIDq];       // fp16 wv
__device__ __half g_woh[(size_t)HIDq * Hq * Dq];        // fp16 wo
__device__ __half g_attnh[(size_t)Bq * Sq * Hq * Dq];   // fp16 attn out [B,S,H*D]
__device__ float g_projq[(size_t)Bq * Sq * Hq * Dq];    // raw Q projection
__device__ float g_projk[(size_t)Bq * Sq * KVq * Dq];   // raw K projection
__device__ float g_projv[(size_t)Bq * Sq * KVq * Dq];   // raw V projection
__device__ float g_q[(size_t)Bq * Hq * Sq * Dq];        // [B,H,S,D]
__device__ float g_k[(size_t)Bq * KVq * Sq * Dq];       // [B,KV,S,D]
__device__ float g_v[(size_t)Bq * KVq * Sq * Dq];       // [B,KV,S,D]

// ---------------------------------------------------------------------------
// ONE fused fp32 -> fp16 conversion for all five inputs.
// ---------------------------------------------------------------------------
#define HS4  ((size_t)Bq * Sq * HIDq / 4)          // 4,194,304
#define WQ4  ((size_t)Hq * Dq * HIDq / 4)          // 4,194,304
#define WKV4 ((size_t)KVq * Dq * HIDq / 4)         // 1,048,576
#define WO4  ((size_t)HIDq * Hq * Dq / 4)          // 4,194,304
#define CONV_TOTAL (HS4 + WQ4 + 2 * WKV4 + WO4)    // 14,680,064

__global__ __launch_bounds__(256)
void conv_all(const float4* __restrict__ hs, const float4* __restrict__ wq,
              const float4* __restrict__ wk, const float4* __restrict__ wv,
              const float4* __restrict__ wo)
{
    size_t i = (size_t)blockIdx.x * blockDim.x + threadIdx.x;
    const float4* src;
    __half* dst;
    if (i < HS4)                          { src = hs; dst = g_hsh; }
    else if (i < HS4 + WQ4)               { i -= HS4; src = wq; dst = g_wqh; }
    else if (i < HS4 + WQ4 + WKV4)        { i -= HS4 + WQ4; src = wk; dst = g_wkh; }
    else if (i < HS4 + WQ4 + 2 * WKV4)    { i -= HS4 + WQ4 + WKV4; src = wv; dst = g_wvh; }
    else if (i < CONV_TOTAL)              { i -= HS4 + WQ4 + 2 * WKV4; src = wo; dst = g_woh; }
    else return;
    float4 v = src[i];
    __half2* d2 = (__half2*)(dst + i * 4);
    d2[0] = __floats2half2_rn(v.x, v.y);
    d2[1] = __floats2half2_rn(v.z, v.w);
}

// ---------------------------------------------------------------------------
// fp16 tensor-core NT GEMM with 4-stage cp.async pipeline.
// C[m,n] = sum_k A[m,k] * W[n,k], fp32 accumulate.
// BM=BN=128, BK=32, 256 threads (8 warps), warp tile 64x32,
// mma.sync.m16n8k16.f16 (2 k-steps per iter). niter = K/32.
// LDH=40 halves/row: conflict-free fragment LDS, 16B-aligned cp.async rows.
// ---------------------------------------------------------------------------
__device__ __forceinline__ void mma_f16(float& d0, float& d1, float& d2, float& d3,
                                        uint32_t a0, uint32_t a1, uint32_t a2, uint32_t a3,
                                        uint32_t b0, uint32_t b1) {
    asm volatile(
        "mma.sync.aligned.m16n8k16.row.col.f32.f16.f16.f32 "
        "{%0,%1,%2,%3}, {%4,%5,%6,%7}, {%8,%9}, {%0,%1,%2,%3};"
        : "+f"(d0), "+f"(d1), "+f"(d2), "+f"(d3)
        : "r"(a0), "r"(a1), "r"(a2), "r"(a3), "r"(b0), "r"(b1));
}

__device__ __forceinline__ void cp16(void* dst, const void* src) {
    uint32_t d = (uint32_t)__cvta_generic_to_shared(dst);
    asm volatile("cp.async.ca.shared.global [%0], [%1], 16;" :: "r"(d), "l"(src));
}

#define LDH     40
#define LDH32   20
#define TILEH   (128 * LDH)
#define STAGES  4
#define GEMM_SMEM_BYTES (STAGES * 2 * TILEH * 2)   // 81,920

__global__ __launch_bounds__(256, 2)
void gemm_h(int asel, int wsel, float* __restrict__ Cparam,
            int M, int N, int K, int csel)
{
    extern __shared__ __half hsm[];
    __half* Asm = hsm;                    // [STAGES][TILEH]
    __half* Bsm = hsm + STAGES * TILEH;

    const __half* A = asel ? g_attnh : g_hsh;
    const __half* W = (wsel == 0) ? g_wqh
                    : (wsel == 1) ? g_wkh
                    : (wsel == 2) ? g_wvh : g_woh;
    float* C = (csel == 0) ? Cparam
             : (csel == 1) ? g_projq
             : (csel == 2) ? g_projk : g_projv;

    const int tid  = threadIdx.x;
    const int lane = tid & 31;
    const int w    = tid >> 5;
    const int wm   = (w >> 2) * 64;
    const int wn   = (w & 3) * 32;
    const int gid  = lane >> 2;
    const int tig  = lane & 3;

    const int m0 = blockIdx.y * 128;
    const int n0 = blockIdx.x * 128;

    const int lrow = tid >> 1;          // 0..127
    const int c8   = (tid & 1) << 4;    // 0 or 16 (halves)

    const __half* Arow = A + (size_t)(m0 + lrow) * K + c8;
    const __half* Wrow = W + (size_t)(n0 + lrow) * K + c8;
    __half* AsmRow = Asm + lrow * LDH + c8;
    __half* BsmRow = Bsm + lrow * LDH + c8;

    float acc[4][4][4];
#pragma unroll
    for (int mt = 0; mt < 4; mt++)
#pragma unroll
        for (int nt = 0; nt < 4; nt++)
#pragma unroll
            for (int e = 0; e < 4; e++) acc[mt][nt][e] = 0.f;

    const int niter = K >> 5;   // K/32

    // Prologue: stages 0,1,2 in flight (3 groups).
#pragma unroll
    for (int s = 0; s < 3; s++) {
        const int k0 = s << 5;
        cp16(AsmRow + s * TILEH,     Arow + k0);
        cp16(AsmRow + s * TILEH + 8, Arow + k0 + 8);
        cp16(BsmRow + s * TILEH,     Wrow + k0);
        cp16(BsmRow + s * TILEH + 8, Wrow + k0 + 8);
        asm volatile("cp.async.commit_group;");
    }

    for (int i = 0; i < niter; i++) {
        // commits so far = 3 + i; all but newest 2 done => group i done.
        asm volatile("cp.async.wait_group 2;");
        __syncthreads();

        if (i + 3 < niter) {
            const int s = (i + 3) % STAGES;
            const int k0 = (i + 3) << 5;
            cp16(AsmRow + s * TILEH,     Arow + k0);
            cp16(AsmRow + s * TILEH + 8, Arow + k0 + 8);
            cp16(BsmRow + s * TILEH,     Wrow + k0);
            cp16(BsmRow + s * TILEH + 8, Wrow + k0 + 8);
        }
        asm volatile("cp.async.commit_group;");  // unconditional: count exact

        const uint32_t* Ac = (const uint32_t*)(Asm + (i % STAGES) * TILEH);
        const uint32_t* Bc = (const uint32_t*)(Bsm + (i % STAGES) * TILEH);
#pragma unroll
        for (int ks = 0; ks < 2; ks++) {
            const int kw = ks * 8;
            uint32_t af[4][4];
#pragma unroll
            for (int mt = 0; mt < 4; mt++) {
                const int rbase = wm + mt * 16 + gid;
                af[mt][0] = Ac[(rbase    ) * LDH32 + kw + tig    ];
                af[mt][1] = Ac[(rbase + 8) * LDH32 + kw + tig    ];
                af[mt][2] = Ac[(rbase    ) * LDH32 + kw + tig + 4];
                af[mt][3] = Ac[(rbase + 8) * LDH32 + kw + tig + 4];
            }
            uint32_t bf[4][2];
#pragma unroll
            for (int nt = 0; nt < 4; nt++) {
                const int nrow = wn + nt * 8 + gid;
                bf[nt][0] = Bc[nrow * LDH32 + kw + tig    ];
                bf[nt][1] = Bc[nrow * LDH32 + kw + tig + 4];
            }
#pragma unroll
            for (int mt = 0; mt < 4; mt++)
#pragma unroll
                for (int nt = 0; nt < 4; nt++)
                    mma_f16(acc[mt][nt][0], acc[mt][nt][1],
                            acc[mt][nt][2], acc[mt][nt][3],
                            af[mt][0], af[mt][1], af[mt][2], af[mt][3],
                            bf[nt][0], bf[nt][1]);
        }
    }

#pragma unroll
    for (int mt = 0; mt < 4; mt++) {
#pragma unroll
        for (int nt = 0; nt < 4; nt++) {
            const int n = n0 + wn + nt * 8 + 2 * tig;
            const int mA = m0 + wm + mt * 16 + gid;
            float2 v01; v01.x = acc[mt][nt][0]; v01.y = acc[mt][nt][1];
            float2 v23; v23.x = acc[mt][nt][2]; v23.y = acc[mt][nt][3];
            *(float2*)(C + (size_t)mA * N + n)       = v01;
            *(float2*)(C + (size_t)(mA + 8) * N + n) = v23;
        }
    }
}

// ---------------------------------------------------------------------------
// Fused RoPE + transpose for Q, K, V (unchanged - PASSING)
// ---------------------------------------------------------------------------
#define QPAIRS ((size_t)Bq * Sq * Hq * (Dq / 2))
#define KPAIRS ((size_t)Bq * Sq * KVq * (Dq / 2))

__global__ __launch_bounds__(256)
void rope_all(const float* __restrict__ cosp, const float* __restrict__ sinp)
{
    size_t idx = (size_t)blockIdx.x * blockDim.x + threadIdx.x;
    const float* src;
    float* dst;
    int Hh, dorope;
    if (idx < QPAIRS) {
        src = g_projq; dst = g_q; Hh = Hq; dorope = 1;
    } else if (idx < QPAIRS + KPAIRS) {
        idx -= QPAIRS;
        src = g_projk; dst = g_k; Hh = KVq; dorope = 1;
    } else if (idx < QPAIRS + 2 * KPAIRS) {
        idx -= QPAIRS + KPAIRS;
        src = g_projv; dst = g_v; Hh = KVq; dorope = 0;
    } else {
        return;
    }

    const int dpair = (int)(idx % (Dq / 2));
    size_t rest = idx / (Dq / 2);
    const int hh = (int)(rest % Hh);  rest /= Hh;
    const int s  = (int)(rest % Sq);
    const int b  = (int)(rest / Sq);
    const int d  = dpair * 2;

    const size_t srcix = ((size_t)(b * Sq + s) * Hh + hh) * Dq + d;
    float v0 = src[srcix];
    float v1 = src[srcix + 1];
    if (dorope) {
        const float c  = cosp[s * Dq + d];
        const float sn = sinp[s * Dq + d];
        const float t0 = v0 * c - v1 * sn;
        const float t1 = v1 * c + v0 * sn;
        v0 = t0; v1 = t1;
    }
    const size_t o = (((size_t)b * Hh + hh) * Sq + s) * Dq + d;
    dst[o]     = v0;
    dst[o + 1] = v1;
}

// ---------------------------------------------------------------------------
// Flash attention v3 (unchanged - PASSING). fp16 output to g_attnh.
// ---------------------------------------------------------------------------
#define LDP 130
#define FLASH_FLOATS (64 * LDP + 32 * LDP + 32 * 128)

__global__ __launch_bounds__(256)
void flash_v3()
{
    extern __shared__ float sm[];
    float* Qs = sm;
    float* Ks = Qs + 64 * LDP;
    float* Vs = Ks + 32 * LDP;

    const int qb = blockIdx.x;
    const int h  = blockIdx.y;
    const int b  = blockIdx.z;
    const int kh = h / Gq;
    const int tid = threadIdx.x;
    const int r = tid >> 2;
    const int q = tid & 3;
    const float scale = 0.08838834764831845f;

    const float* Qg = g_q + (((size_t)b * Hq  + h ) * Sq + (size_t)qb * 64) * Dq;
    const float* Kg = g_k + (((size_t)b * KVq + kh) * Sq) * Dq;
    const float* Vg = g_v + (((size_t)b * KVq + kh) * Sq) * Dq;

#pragma unroll
    for (int i = 0; i < 8; i++) {
        const int idx = tid + i * 256;
        const int rr = idx >> 5;
        const int c4 = (idx & 31) << 2;
        float4 v = *(const float4*)(Qg + rr * Dq + c4);
        Qs[rr * LDP + c4 + 0] = v.x;
        Qs[rr * LDP + c4 + 1] = v.y;
        Qs[rr * LDP + c4 + 2] = v.z;
        Qs[rr * LDP + c4 + 3] = v.w;
    }

    float m_i = -INFINITY;
    float l_i = 0.f;
    float o[32];
#pragma unroll
    for (int j = 0; j < 32; j++) o[j] = 0.f;

    const int qr = qb * 64 + r;
    const int ntiles = 2 * qb + 2;

    for (int cb = 0; cb < ntiles; cb++) {
        __syncthreads();
#pragma unroll
        for (int i = 0; i < 4; i++) {
            const int idx = tid + i * 256;
            const int rr = idx >> 5;
            const int c4 = (idx & 31) << 2;
            float4 kv = *(const float4*)(Kg + (size_t)(cb * 32 + rr) * Dq + c4);
            Ks[rr * LDP + c4 + 0] = kv.x;
            Ks[rr * LDP + c4 + 1] = kv.y;
            Ks[rr * LDP + c4 + 2] = kv.z;
            Ks[rr * LDP + c4 + 3] = kv.w;
            float4 vv = *(const float4*)(Vg + (size_t)(cb * 32 + rr) * Dq + c4);
            *(float4*)(Vs + rr * 128 + c4) = vv;
        }
        __syncthreads();

        float s8[8];
#pragma unroll
        for (int j = 0; j < 8; j++) s8[j] = 0.f;
        const float* qrow = Qs + r * LDP;
#pragma unroll 4
        for (int k = 0; k < 128; k++) {
            const float qv = qrow[k];
#pragma unroll
            for (int j = 0; j < 8; j++)
                s8[j] += qv * Ks[(q * 8 + j) * LDP + k];
        }
        __syncthreads();

        float mx = -INFINITY;
#pragma unroll
        for (int j = 0; j < 8; j++) {
            const int kc = cb * 32 + q * 8 + j;
            s8[j] = (kc <= qr) ? s8[j] * scale : -INFINITY;
            mx = fmaxf(mx, s8[j]);
        }
        mx = fmaxf(mx, __shfl_xor_sync(0xffffffffu, mx, 1));
        mx = fmaxf(mx, __shfl_xor_sync(0xffffffffu, mx, 2));
        const float m_new = fmaxf(m_i, mx);
        const float corr  = __expf(m_i - m_new);
        float lsum = 0.f;
#pragma unroll
        for (int j = 0; j < 8; j++) {
            s8[j] = __expf(s8[j] - m_new);
            lsum += s8[j];
        }
        lsum += __shfl_xor_sync(0xffffffffu, lsum, 1);
        lsum += __shfl_xor_sync(0xffffffffu, lsum, 2);
        l_i = l_i * corr + lsum;
        m_i = m_new;
#pragma unroll
        for (int j = 0; j < 32; j++) o[j] *= corr;
#pragma unroll
        for (int j = 0; j < 8; j++)
            Ks[(q * 8 + j) * LDP + r] = s8[j];
        __syncthreads();

        for (int c = 0; c < 32; c++) {
            const float pv = Ks[c * LDP + r];
            const float* vrow = Vs + c * 128 + q * 4;
#pragma unroll
            for (int j = 0; j < 8; j++) {
                float4 v4 = *(const float4*)(vrow + j * 16);
                o[j * 4 + 0] += pv * v4.x;
                o[j * 4 + 1] += pv * v4.y;
                o[j * 4 + 2] += pv * v4.z;
                o[j * 4 + 3] += pv * v4.w;
            }
        }
    }

    const float inv = 1.f / l_i;
    __half* og = g_attnh + ((size_t)(b * Sq + qr) * Hq + h) * Dq + q * 4;
#pragma unroll
    for (int j = 0; j < 8; j++) {
        *(__half2*)(og + j * 16)     = __floats2half2_rn(o[j * 4 + 0] * inv,
                                                         o[j * 4 + 1] * inv);
        *(__half2*)(og + j * 16 + 2) = __floats2half2_rn(o[j * 4 + 2] * inv,
                                                         o[j * 4 + 3] * inv);
    }
}

// ---------------------------------------------------------------------------
// Launcher. Order: conv(0), gemm_k(1), gemm_v(2), gemm_q(3) <- ncu capture,
// rope(4), flash(5), gemm_o(6).
// ---------------------------------------------------------------------------
extern "C" void kernel_launch(void* const* d_in, const int* in_sizes, int n_in,
                              void* d_out, int out_size)
{
    const float *hs, *cosp, *sinp, *wq, *wk, *wv, *wo;
    if (in_sizes[0] == Bq * Sq * HIDq) {
        hs   = (const float*)d_in[0];
        cosp = (const float*)d_in[1];
        sinp = (const float*)d_in[2];
        wq   = (const float*)d_in[3];
        wk   = (const float*)d_in[4];
        wv   = (const float*)d_in[5];
        wo   = (const float*)d_in[6];
    } else {  // alphabetical fallback
        cosp = (const float*)d_in[0];
        hs   = (const float*)d_in[1];
        sinp = (const float*)d_in[2];
        wk   = (const float*)d_in[3];
        wo   = (const float*)d_in[4];
        wq   = (const float*)d_in[5];
        wv   = (const float*)d_in[6];
    }
    float* out = (float*)d_out;

    const dim3 blk(256);
    const int M = Bq * Sq;          // 4096
    const int NQ = Hq * Dq;         // 4096
    const int NKV = KVq * Dq;       // 1024

    // (0) fused fp32 -> fp16 conversion
    conv_all<<<(unsigned)((CONV_TOTAL + 255) / 256), 256>>>(
        (const float4*)hs, (const float4*)wq, (const float4*)wk,
        (const float4*)wv, (const float4*)wo);

    cudaFuncSetAttribute(gemm_h, cudaFuncAttributeMaxDynamicSharedMemorySize,
                         GEMM_SMEM_BYTES);

    // (1)(2) small projections, (3) big Q projection (ncu capture slot)
    gemm_h<<<dim3(NKV / 128, M / 128), blk, GEMM_SMEM_BYTES>>>(0, 1, nullptr, M, NKV, HIDq, 2);
    gemm_h<<<dim3(NKV / 128, M / 128), blk, GEMM_SMEM_BYTES>>>(0, 2, nullptr, M, NKV, HIDq, 3);
    gemm_h<<<dim3(NQ / 128, M / 128), blk, GEMM_SMEM_BYTES>>>(0, 0, nullptr, M, NQ, HIDq, 1);

    // (4) fused RoPE/transpose
    {
        size_t total = QPAIRS + 2 * KPAIRS;
        rope_all<<<(unsigned)((total + 255) / 256), 256>>>(cosp, sinp);
    }

    // (5) flash attention -> g_attnh (fp16)
    const int smem_bytes = FLASH_FLOATS * (int)sizeof(float);  // 66,304
    cudaFuncSetAttribute(flash_v3, cudaFuncAttributeMaxDynamicSharedMemorySize,
                         smem_bytes);
    flash_v3<<<dim3(Sq / 64, Hq, Bq), blk, smem_bytes>>>();

    // (6) output projection
    gemm_h<<<dim3(HIDq / 128, M / 128), blk, GEMM_SMEM_BYTES>>>(1, 3, out, M, HIDq, NQ, 0);
}

// round 17
// speedup vs baseline: 3.7883x; 3.7883x over previous
#include <cuda_runtime.h>
#include <cuda_fp16.h>
#include <math.h>
#include <stdint.h>

// Problem constants
#define Bq   2
#define Sq   2048
#define HIDq 4096
#define Hq   32
#define KVq  8
#define Dq   128
#define Gq   (Hq / KVq)

// Scratch buffers (allocation-free rule: __device__ globals)
__device__ __half g_hsh[(size_t)Bq * Sq * HIDq];        // fp16 hidden_states
__device__ __half g_wqh[(size_t)Hq * Dq * HIDq];        // fp16 wq
__device__ __half g_wkh[(size_t)KVq * Dq * HIDq];       // fp16 wk
__device__ __half g_wvh[(size_t)KVq * Dq * HIDq];       // fp16 wv
__device__ __half g_woh[(size_t)HIDq * Hq * Dq];        // fp16 wo
__device__ __half g_attnh[(size_t)Bq * Sq * Hq * Dq];   // fp16 attn out [B,S,H*D]
__device__ float g_projq[(size_t)Bq * Sq * Hq * Dq];    // raw Q projection
__device__ float g_projk[(size_t)Bq * Sq * KVq * Dq];   // raw K projection
__device__ float g_projv[(size_t)Bq * Sq * KVq * Dq];   // raw V projection
__device__ __half g_qh[(size_t)Bq * Hq * Sq * Dq];      // fp16 [B,H,S,D]
__device__ __half g_kh[(size_t)Bq * KVq * Sq * Dq];     // fp16 [B,KV,S,D]
__device__ __half g_vh[(size_t)Bq * KVq * Sq * Dq];     // fp16 [B,KV,S,D]

// ---------------------------------------------------------------------------
// ONE fused fp32 -> fp16 conversion for all five inputs.
// ---------------------------------------------------------------------------
#define HS4  ((size_t)Bq * Sq * HIDq / 4)
#define WQ4  ((size_t)Hq * Dq * HIDq / 4)
#define WKV4 ((size_t)KVq * Dq * HIDq / 4)
#define WO4  ((size_t)HIDq * Hq * Dq / 4)
#define CONV_TOTAL (HS4 + WQ4 + 2 * WKV4 + WO4)

__global__ __launch_bounds__(256)
void conv_all(const float4* __restrict__ hs, const float4* __restrict__ wq,
              const float4* __restrict__ wk, const float4* __restrict__ wv,
              const float4* __restrict__ wo)
{
    size_t i = (size_t)blockIdx.x * blockDim.x + threadIdx.x;
    const float4* src;
    __half* dst;
    if (i < HS4)                          { src = hs; dst = g_hsh; }
    else if (i < HS4 + WQ4)               { i -= HS4; src = wq; dst = g_wqh; }
    else if (i < HS4 + WQ4 + WKV4)        { i -= HS4 + WQ4; src = wk; dst = g_wkh; }
    else if (i < HS4 + WQ4 + 2 * WKV4)    { i -= HS4 + WQ4 + WKV4; src = wv; dst = g_wvh; }
    else if (i < CONV_TOTAL)              { i -= HS4 + WQ4 + 2 * WKV4; src = wo; dst = g_woh; }
    else return;
    float4 v = src[i];
    __half2* d2 = (__half2*)(dst + i * 4);
    d2[0] = __floats2half2_rn(v.x, v.y);
    d2[1] = __floats2half2_rn(v.z, v.w);
}

// ---------------------------------------------------------------------------
// mma helpers
// ---------------------------------------------------------------------------
__device__ __forceinline__ void mma_f16(float& d0, float& d1, float& d2, float& d3,
                                        uint32_t a0, uint32_t a1, uint32_t a2, uint32_t a3,
                                        uint32_t b0, uint32_t b1) {
    asm volatile(
        "mma.sync.aligned.m16n8k16.row.col.f32.f16.f16.f32 "
        "{%0,%1,%2,%3}, {%4,%5,%6,%7}, {%8,%9}, {%0,%1,%2,%3};"
        : "+f"(d0), "+f"(d1), "+f"(d2), "+f"(d3)
        : "r"(a0), "r"(a1), "r"(a2), "r"(a3), "r"(b0), "r"(b1));
}

__device__ __forceinline__ void cp16(void* dst, const void* src) {
    uint32_t d = (uint32_t)__cvta_generic_to_shared(dst);
    asm volatile("cp.async.ca.shared.global [%0], [%1], 16;" :: "r"(d), "l"(src));
}

__device__ __forceinline__ uint32_t pack_h2(float x, float y) {
    __half2 t = __floats2half2_rn(x, y);
    return *reinterpret_cast<uint32_t*>(&t);
}

// ---------------------------------------------------------------------------
// fp16 tensor-core NT GEMM, 4-stage cp.async (unchanged from R16 - PASSING)
// ---------------------------------------------------------------------------
#define LDH     40
#define LDH32   20
#define TILEH   (128 * LDH)
#define STAGES  4
#define GEMM_SMEM_BYTES (STAGES * 2 * TILEH * 2)   // 81,920

__global__ __launch_bounds__(256, 2)
void gemm_h(int asel, int wsel, float* __restrict__ Cparam,
            int M, int N, int K, int csel)
{
    extern __shared__ __half hsm[];
    __half* Asm = hsm;
    __half* Bsm = hsm + STAGES * TILEH;

    const __half* A = asel ? g_attnh : g_hsh;
    const __half* W = (wsel == 0) ? g_wqh
                    : (wsel == 1) ? g_wkh
                    : (wsel == 2) ? g_wvh : g_woh;
    float* C = (csel == 0) ? Cparam
             : (csel == 1) ? g_projq
             : (csel == 2) ? g_projk : g_projv;

    const int tid  = threadIdx.x;
    const int lane = tid & 31;
    const int w    = tid >> 5;
    const int wm   = (w >> 2) * 64;
    const int wn   = (w & 3) * 32;
    const int gid  = lane >> 2;
    const int tig  = lane & 3;

    const int m0 = blockIdx.y * 128;
    const int n0 = blockIdx.x * 128;

    const int lrow = tid >> 1;
    const int c8   = (tid & 1) << 4;

    const __half* Arow = A + (size_t)(m0 + lrow) * K + c8;
    const __half* Wrow = W + (size_t)(n0 + lrow) * K + c8;
    __half* AsmRow = Asm + lrow * LDH + c8;
    __half* BsmRow = Bsm + lrow * LDH + c8;

    float acc[4][4][4];
#pragma unroll
    for (int mt = 0; mt < 4; mt++)
#pragma unroll
        for (int nt = 0; nt < 4; nt++)
#pragma unroll
            for (int e = 0; e < 4; e++) acc[mt][nt][e] = 0.f;

    const int niter = K >> 5;

#pragma unroll
    for (int s = 0; s < 3; s++) {
        const int k0 = s << 5;
        cp16(AsmRow + s * TILEH,     Arow + k0);
        cp16(AsmRow + s * TILEH + 8, Arow + k0 + 8);
        cp16(BsmRow + s * TILEH,     Wrow + k0);
        cp16(BsmRow + s * TILEH + 8, Wrow + k0 + 8);
        asm volatile("cp.async.commit_group;");
    }

    for (int i = 0; i < niter; i++) {
        asm volatile("cp.async.wait_group 2;");
        __syncthreads();

        if (i + 3 < niter) {
            const int s = (i + 3) % STAGES;
            const int k0 = (i + 3) << 5;
            cp16(AsmRow + s * TILEH,     Arow + k0);
            cp16(AsmRow + s * TILEH + 8, Arow + k0 + 8);
            cp16(BsmRow + s * TILEH,     Wrow + k0);
            cp16(BsmRow + s * TILEH + 8, Wrow + k0 + 8);
        }
        asm volatile("cp.async.commit_group;");

        const uint32_t* Ac = (const uint32_t*)(Asm + (i % STAGES) * TILEH);
        const uint32_t* Bc = (const uint32_t*)(Bsm + (i % STAGES) * TILEH);
#pragma unroll
        for (int ks = 0; ks < 2; ks++) {
            const int kw = ks * 8;
            uint32_t af[4][4];
#pragma unroll
            for (int mt = 0; mt < 4; mt++) {
                const int rbase = wm + mt * 16 + gid;
                af[mt][0] = Ac[(rbase    ) * LDH32 + kw + tig    ];
                af[mt][1] = Ac[(rbase + 8) * LDH32 + kw + tig    ];
                af[mt][2] = Ac[(rbase    ) * LDH32 + kw + tig + 4];
                af[mt][3] = Ac[(rbase + 8) * LDH32 + kw + tig + 4];
            }
            uint32_t bf[4][2];
#pragma unroll
            for (int nt = 0; nt < 4; nt++) {
                const int nrow = wn + nt * 8 + gid;
                bf[nt][0] = Bc[nrow * LDH32 + kw + tig    ];
                bf[nt][1] = Bc[nrow * LDH32 + kw + tig + 4];
            }
#pragma unroll
            for (int mt = 0; mt < 4; mt++)
#pragma unroll
                for (int nt = 0; nt < 4; nt++)
                    mma_f16(acc[mt][nt][0], acc[mt][nt][1],
                            acc[mt][nt][2], acc[mt][nt][3],
                            af[mt][0], af[mt][1], af[mt][2], af[mt][3],
                            bf[nt][0], bf[nt][1]);
        }
    }

#pragma unroll
    for (int mt = 0; mt < 4; mt++) {
#pragma unroll
        for (int nt = 0; nt < 4; nt++) {
            const int n = n0 + wn + nt * 8 + 2 * tig;
            const int mA = m0 + wm + mt * 16 + gid;
            float2 v01; v01.x = acc[mt][nt][0]; v01.y = acc[mt][nt][1];
            float2 v23; v23.x = acc[mt][nt][2]; v23.y = acc[mt][nt][3];
            *(float2*)(C + (size_t)mA * N + n)       = v01;
            *(float2*)(C + (size_t)(mA + 8) * N + n) = v23;
        }
    }
}

// ---------------------------------------------------------------------------
// Fused RoPE + transpose, now emitting fp16 g_qh/g_kh/g_vh.
// ---------------------------------------------------------------------------
#define QPAIRS ((size_t)Bq * Sq * Hq * (Dq / 2))
#define KPAIRS ((size_t)Bq * Sq * KVq * (Dq / 2))

__global__ __launch_bounds__(256)
void rope_all(const float* __restrict__ cosp, const float* __restrict__ sinp)
{
    size_t idx = (size_t)blockIdx.x * blockDim.x + threadIdx.x;
    const float* src;
    __half* dst;
    int Hh, dorope;
    if (idx < QPAIRS) {
        src = g_projq; dst = g_qh; Hh = Hq; dorope = 1;
    } else if (idx < QPAIRS + KPAIRS) {
        idx -= QPAIRS;
        src = g_projk; dst = g_kh; Hh = KVq; dorope = 1;
    } else if (idx < QPAIRS + 2 * KPAIRS) {
        idx -= QPAIRS + KPAIRS;
        src = g_projv; dst = g_vh; Hh = KVq; dorope = 0;
    } else {
        return;
    }

    const int dpair = (int)(idx % (Dq / 2));
    size_t rest = idx / (Dq / 2);
    const int hh = (int)(rest % Hh);  rest /= Hh;
    const int s  = (int)(rest % Sq);
    const int b  = (int)(rest / Sq);
    const int d  = dpair * 2;

    const size_t srcix = ((size_t)(b * Sq + s) * Hh + hh) * Dq + d;
    float v0 = src[srcix];
    float v1 = src[srcix + 1];
    if (dorope) {
        const float c  = cosp[s * Dq + d];
        const float sn = sinp[s * Dq + d];
        const float t0 = v0 * c - v1 * sn;
        const float t1 = v1 * c + v0 * sn;
        v0 = t0; v1 = t1;
    }
    const size_t o = (((size_t)b * Hh + hh) * Sq + s) * Dq + d;
    *(__half2*)&dst[o] = __floats2half2_rn(v0, v1);
}

// ---------------------------------------------------------------------------
// Tensor-core flash attention. Br=128, Bc=64, 8 warps; warp w owns rows
// [w*16, w*16+16). QK^T and PV via mma.m16n8k16 (fp32 accum). P stays in
// registers (C-fragment of QK^T == A-fragment of PV). V stored d-major
// (transposed) for B-fragment loads.
// Fragment index math identical to gemm_h (proven).
// grid = (S/128, H, B), 256 threads.
// ---------------------------------------------------------------------------
#define QLDH 136     // halves per Q/K smem row (128 + 8 pad)
#define QLDW 68      // b32 words per row
#define VLDH 74      // halves per Vt row (64 + 10 pad; odd word stride)
#define VLDW 37
#define FLASH_SMEM_BYTES ((128 * QLDH + 64 * QLDH + 128 * VLDH) * 2)  // 71,168

__global__ __launch_bounds__(256)
void flash_mma()
{
    extern __shared__ __half fsm[];
    __half* Qs = fsm;                  // [128][QLDH]
    __half* Ks = Qs + 128 * QLDH;      // [64][QLDH]
    __half* Vt = Ks + 64 * QLDH;       // [128][VLDH], d-major (transposed V)
    const uint32_t* Qw = (const uint32_t*)Qs;
    const uint32_t* Kw = (const uint32_t*)Ks;
    const uint32_t* Vw = (const uint32_t*)Vt;

    const int qb = blockIdx.x;
    const int h  = blockIdx.y;
    const int b  = blockIdx.z;
    const int kh = h / Gq;
    const int tid  = threadIdx.x;
    const int lane = tid & 31;
    const int w    = tid >> 5;         // warp 0..7
    const int gid  = lane >> 2;        // 0..7
    const int tig  = lane & 3;         // 0..3
    const int rq   = w * 16;           // warp row base in Q tile
    const float scale = 0.08838834764831845f;  // 1/sqrt(128)

    const __half* Qg = g_qh + (((size_t)b * Hq + h) * Sq + (size_t)qb * 128) * Dq;
    const __half* Kg = g_kh + ((size_t)b * KVq + kh) * Sq * Dq;
    const __half* Vg = g_vh + ((size_t)b * KVq + kh) * Sq * Dq;

    // Load Q tile (128x128 halves = 2048 x 16B chunks, 8 per thread)
#pragma unroll
    for (int i = 0; i < 8; i++) {
        const int idx = tid + i * 256;
        const int row = idx >> 4;
        const int c8  = (idx & 15) * 8;
        *(uint4*)&Qs[row * QLDH + c8] = *(const uint4*)&Qg[row * Dq + c8];
    }

    float m0 = -INFINITY, m1 = -INFINITY, l0 = 0.f, l1 = 0.f;
    float o[16][4];
#pragma unroll
    for (int nd = 0; nd < 16; nd++)
#pragma unroll
        for (int e = 0; e < 4; e++) o[nd][e] = 0.f;

    const int qr0 = qb * 128 + rq + gid;
    const int qr1 = qr0 + 8;
    const int ntiles = 2 * qb + 2;

    for (int cb = 0; cb < ntiles; cb++) {
        __syncthreads();   // prev tile fully consumed; Q visible at cb=0
        // K tile (64x128 halves = 1024 chunks, 4 per thread)
#pragma unroll
        for (int i = 0; i < 4; i++) {
            const int idx = tid + i * 256;
            const int row = idx >> 4;
            const int c8  = (idx & 15) * 8;
            *(uint4*)&Ks[row * QLDH + c8] =
                *(const uint4*)&Kg[(size_t)(cb * 64 + row) * Dq + c8];
        }
        // V tile, transposed into Vt[d][s]
#pragma unroll
        for (int i = 0; i < 4; i++) {
            const int idx = tid + i * 256;
            const int s  = idx >> 4;
            const int d0 = (idx & 15) * 8;
            uint4 v = *(const uint4*)&Vg[(size_t)(cb * 64 + s) * Dq + d0];
            const __half* hv = (const __half*)&v;
#pragma unroll
            for (int j = 0; j < 8; j++)
                Vt[(d0 + j) * VLDH + s] = hv[j];
        }
        __syncthreads();

        // S = Q K^T : 8 k-steps x 8 n-tiles
        float sacc[8][4];
#pragma unroll
        for (int nt = 0; nt < 8; nt++)
#pragma unroll
            for (int e = 0; e < 4; e++) sacc[nt][e] = 0.f;
#pragma unroll
        for (int kt = 0; kt < 8; kt++) {
            const int kw = kt * 8;
            const uint32_t a0 = Qw[(rq + gid    ) * QLDW + kw + tig    ];
            const uint32_t a1 = Qw[(rq + gid + 8) * QLDW + kw + tig    ];
            const uint32_t a2 = Qw[(rq + gid    ) * QLDW + kw + tig + 4];
            const uint32_t a3 = Qw[(rq + gid + 8) * QLDW + kw + tig + 4];
#pragma unroll
            for (int nt = 0; nt < 8; nt++) {
                const uint32_t b0 = Kw[(nt * 8 + gid) * QLDW + kw + tig    ];
                const uint32_t b1 = Kw[(nt * 8 + gid) * QLDW + kw + tig + 4];
                mma_f16(sacc[nt][0], sacc[nt][1], sacc[nt][2], sacc[nt][3],
                        a0, a1, a2, a3, b0, b1);
            }
        }

        // Mask + scale + row max (C layout: rows gid,gid+8; cols nt*8+2tig+{0,1})
        float mx0 = -INFINITY, mx1 = -INFINITY;
#pragma unroll
        for (int nt = 0; nt < 8; nt++) {
            const int kc = cb * 64 + nt * 8 + 2 * tig;
            sacc[nt][0] = (kc     <= qr0) ? sacc[nt][0] * scale : -INFINITY;
            sacc[nt][1] = (kc + 1 <= qr0) ? sacc[nt][1] * scale : -INFINITY;
            sacc[nt][2] = (kc     <= qr1) ? sacc[nt][2] * scale : -INFINITY;
            sacc[nt][3] = (kc + 1 <= qr1) ? sacc[nt][3] * scale : -INFINITY;
            mx0 = fmaxf(mx0, fmaxf(sacc[nt][0], sacc[nt][1]));
            mx1 = fmaxf(mx1, fmaxf(sacc[nt][2], sacc[nt][3]));
        }
        mx0 = fmaxf(mx0, __shfl_xor_sync(0xffffffffu, mx0, 1));
        mx0 = fmaxf(mx0, __shfl_xor_sync(0xffffffffu, mx0, 2));
        mx1 = fmaxf(mx1, __shfl_xor_sync(0xffffffffu, mx1, 1));
        mx1 = fmaxf(mx1, __shfl_xor_sync(0xffffffffu, mx1, 2));
        const float mn0 = fmaxf(m0, mx0);
        const float mn1 = fmaxf(m1, mx1);
        const float cr0 = __expf(m0 - mn0);
        const float cr1 = __expf(m1 - mn1);
        float ls0 = 0.f, ls1 = 0.f;
#pragma unroll
        for (int nt = 0; nt < 8; nt++) {
            sacc[nt][0] = __expf(sacc[nt][0] - mn0);
            sacc[nt][1] = __expf(sacc[nt][1] - mn0);
            sacc[nt][2] = __expf(sacc[nt][2] - mn1);
            sacc[nt][3] = __expf(sacc[nt][3] - mn1);
            ls0 += sacc[nt][0] + sacc[nt][1];
            ls1 += sacc[nt][2] + sacc[nt][3];
        }
        ls0 += __shfl_xor_sync(0xffffffffu, ls0, 1);
        ls0 += __shfl_xor_sync(0xffffffffu, ls0, 2);
        ls1 += __shfl_xor_sync(0xffffffffu, ls1, 1);
        ls1 += __shfl_xor_sync(0xffffffffu, ls1, 2);
        l0 = l0 * cr0 + ls0;  m0 = mn0;
        l1 = l1 * cr1 + ls1;  m1 = mn1;
#pragma unroll
        for (int nd = 0; nd < 16; nd++) {
            o[nd][0] *= cr0; o[nd][1] *= cr0;
            o[nd][2] *= cr1; o[nd][3] *= cr1;
        }

        // O += P V : P C-fragments re-packed as A-fragments (no smem trip)
#pragma unroll
        for (int kt = 0; kt < 4; kt++) {
            const uint32_t a0 = pack_h2(sacc[2 * kt    ][0], sacc[2 * kt    ][1]);
            const uint32_t a1 = pack_h2(sacc[2 * kt    ][2], sacc[2 * kt    ][3]);
            const uint32_t a2 = pack_h2(sacc[2 * kt + 1][0], sacc[2 * kt + 1][1]);
            const uint32_t a3 = pack_h2(sacc[2 * kt + 1][2], sacc[2 * kt + 1][3]);
#pragma unroll
            for (int nd = 0; nd < 16; nd++) {
                const uint32_t b0 = Vw[(nd * 8 + gid) * VLDW + kt * 8 + tig    ];
                const uint32_t b1 = Vw[(nd * 8 + gid) * VLDW + kt * 8 + tig + 4];
                mma_f16(o[nd][0], o[nd][1], o[nd][2], o[nd][3],
                        a0, a1, a2, a3, b0, b1);
            }
        }
    }

    // Finalize + write fp16 to g_attnh [B,S,H*D]
    const float i0 = 1.f / l0;
    const float i1 = 1.f / l1;
    __half* og0 = g_attnh + ((size_t)(b * Sq + qr0) * Hq + h) * Dq;
    __half* og1 = g_attnh + ((size_t)(b * Sq + qr1) * Hq + h) * Dq;
#pragma unroll
    for (int nd = 0; nd < 16; nd++) {
        const int col = nd * 8 + 2 * tig;
        *(__half2*)&og0[col] = __floats2half2_rn(o[nd][0] * i0, o[nd][1] * i0);
        *(__half2*)&og1[col] = __floats2half2_rn(o[nd][2] * i1, o[nd][3] * i1);
    }
}

// ---------------------------------------------------------------------------
// Launcher. conv(0), gemm_k(1), gemm_v(2), gemm_q(3), rope(4), flash(5), o(6)
// ---------------------------------------------------------------------------
extern "C" void kernel_launch(void* const* d_in, const int* in_sizes, int n_in,
                              void* d_out, int out_size)
{
    const float *hs, *cosp, *sinp, *wq, *wk, *wv, *wo;
    if (in_sizes[0] == Bq * Sq * HIDq) {
        hs   = (const float*)d_in[0];
        cosp = (const float*)d_in[1];
        sinp = (const float*)d_in[2];
        wq   = (const float*)d_in[3];
        wk   = (const float*)d_in[4];
        wv   = (const float*)d_in[5];
        wo   = (const float*)d_in[6];
    } else {  // alphabetical fallback
        cosp = (const float*)d_in[0];
        hs   = (const float*)d_in[1];
        sinp = (const float*)d_in[2];
        wk   = (const float*)d_in[3];
        wo   = (const float*)d_in[4];
        wq   = (const float*)d_in[5];
        wv   = (const float*)d_in[6];
    }
    float* out = (float*)d_out;

    const dim3 blk(256);
    const int M = Bq * Sq;          // 4096
    const int NQ = Hq * Dq;         // 4096
    const int NKV = KVq * Dq;       // 1024

    conv_all<<<(unsigned)((CONV_TOTAL + 255) / 256), 256>>>(
        (const float4*)hs, (const float4*)wq, (const float4*)wk,
        (const float4*)wv, (const float4*)wo);

    cudaFuncSetAttribute(gemm_h, cudaFuncAttributeMaxDynamicSharedMemorySize,
                         GEMM_SMEM_BYTES);

    gemm_h<<<dim3(NKV / 128, M / 128), blk, GEMM_SMEM_BYTES>>>(0, 1, nullptr, M, NKV, HIDq, 2);
    gemm_h<<<dim3(NKV / 128, M / 128), blk, GEMM_SMEM_BYTES>>>(0, 2, nullptr, M, NKV, HIDq, 3);
    gemm_h<<<dim3(NQ / 128, M / 128), blk, GEMM_SMEM_BYTES>>>(0, 0, nullptr, M, NQ, HIDq, 1);

    {
        size_t total = QPAIRS + 2 * KPAIRS;
        rope_all<<<(unsigned)((total + 255) / 256), 256>>>(cosp, sinp);
    }

    cudaFuncSetAttribute(flash_mma, cudaFuncAttributeMaxDynamicSharedMemorySize,
                         FLASH_SMEM_BYTES);
    flash_mma<<<dim3(Sq / 128, Hq, Bq), blk, FLASH_SMEM_BYTES>>>();

    gemm_h<<<dim3(HIDq / 128, M / 128), blk, GEMM_SMEM_BYTES>>>(1, 3, out, M, HIDq, NQ, 0);
}